// round 4
// baseline (speedup 1.0000x reference)
#include <cuda_runtime.h>
#include <cstdint>

// ============================================================
// IMDCT as one GEMM (overlap-add folded into K):
//   out[b, j, k2] = sum_{kappa<512} A[j,kappa] * Btilde[kappa,k2]
//   A[j, kappa<256]  = spec[b, kappa, j]        (j <= 4095, else 0)
//   A[j, kappa>=256] = spec[b, kappa-256, j-1]  (j >= 1, else 0)
//   Btilde[kappa,k2] = kern[(k2 + (kappa<256?0:256))*256 + (kappa&255)] * 4/512
// out[b] is the contiguous GEMM result C[4097, 256].
//
// Chunk pair trick: chunks c and c+8 read the SAME spec rows, shifted by one
// column. Load A once per pair as a 132-col tile [t0-4, t0+127], all cp.async
// 16B-aligned; fragment reader uses column offset +4 (half 0) or +3 (half 1).
// ============================================================

#define N_FREQ    256
#define T_FRAMES  4096
#define M_ROWS    4097
#define OUT_PER_B (M_ROWS * 256)

#define M_TILE    128
#define N_TILE    128
#define NUM_PAIRS 8            // K pairs: chunk c (kappa<256) + c+8 (kappa>=256)
#define STAGES    2

#define SROW      136                        // padded row stride (floats)
#define SA        (32 * SROW * 4)            // 17408 bytes (one 32-row panel)
#define STAGE_BYTES (3 * SA)                 // A + B0 + B1 = 52224
#define SMEM_BYTES  (STAGES * STAGE_BYTES)   // 104448

__device__ float g_Bmat[512 * 256];          // [kappa][k2], tf32-RNA rounded

__device__ __forceinline__ uint32_t smem_u32(const void* p) {
    uint32_t a;
    asm("{ .reg .u64 t; cvta.to.shared.u64 t, %1; cvt.u32.u64 %0, t; }" : "=r"(a) : "l"(p));
    return a;
}

__device__ __forceinline__ float round_tf32(float v) {
    uint32_t u;
    asm("cvt.rna.tf32.f32 %0, %1;" : "=r"(u) : "f"(v));
    return __uint_as_float(u);
}

// ---------------- prep: build Btilde ----------------
__global__ void build_bmat_kernel(const float* __restrict__ kern) {
    int i = blockIdx.x * 256 + threadIdx.x;   // 131072
    int kappa = i >> 8;
    int k2    = i & 255;
    int trow  = k2 + ((kappa < 256) ? 0 : 256);
    float v = kern[trow * 256 + (kappa & 255)] * (4.0f / 512.0f);
    g_Bmat[kappa * 256 + k2] = round_tf32(v);
}

// ---------------- stage loader (all cp.async 16B-aligned) ----------------
__device__ __forceinline__ void load_stage(
    const float* __restrict__ specb, const float* __restrict__ bmat,
    int t0, int n0, int pair, uint32_t stage_base, int tid)
{
    const int f0 = pair * 32;

    // A: 32 f-rows x 132 t-cols covering t in [t0-4, t0+127]; 33 groups/row
    for (int i = tid; i < 32 * 33; i += 256) {
        int r = i / 33;
        int q = i - r * 33;
        int lo = t0 - 4 + 4 * q;                      // 16B-aligned (t0 % 128 == 0)
        uint32_t dst = stage_base + (uint32_t)(r * SROW + 4 * q) * 4u;
        int nvalid = 0;
        int loc = 0;
        if (lo >= 0 && lo < T_FRAMES) {
            loc = lo;
            nvalid = T_FRAMES - lo;
            if (nvalid > 4) nvalid = 4;
        }
        const float* src = specb + (size_t)(f0 + r) * T_FRAMES + loc;
        uint32_t sz = (uint32_t)(nvalid * 4);
        asm volatile("cp.async.cg.shared.global [%0], [%1], 16, %2;"
                     :: "r"(dst), "l"(src), "r"(sz));
    }

    // B: two 32x128 panels (kappa = f0+r and 256+f0+r), cols [n0, n0+127]
    for (int i = tid; i < 2048; i += 256) {
        int h = i >> 10;
        int rq = i & 1023;
        int r = rq >> 5;
        int q = rq & 31;
        const float* src = bmat + (size_t)(h * 256 + f0 + r) * 256 + n0 + 4 * q;
        uint32_t dst = stage_base + (uint32_t)SA * (1 + h)
                     + (uint32_t)(r * SROW + 4 * q) * 4u;
        asm volatile("cp.async.cg.shared.global [%0], [%1], 16;"
                     :: "r"(dst), "l"(src));
    }
}

#define CP_COMMIT() asm volatile("cp.async.commit_group;" ::: "memory")
#define CP_WAIT1()  asm volatile("cp.async.wait_group 1;" ::: "memory")

// ---------------- main GEMM kernel ----------------
__global__ void __launch_bounds__(256, 2)
imdct_gemm_kernel(const float* __restrict__ spec, float* __restrict__ out)
{
    extern __shared__ __align__(16) float smemf[];
    const uint32_t sb = smem_u32(smemf);

    const int tid = threadIdx.x;
    const int wid = tid >> 5;
    const int lid = tid & 31;
    const int wm  = wid & 1;          // 2 warps along M (64 rows each)
    const int wn  = wid >> 1;         // 4 warps along N (32 cols each)
    const int tg  = lid & 3;
    const int g   = lid >> 2;

    const int t0 = blockIdx.x * M_TILE;         // 33 tiles cover 4097 rows
    const int n0 = blockIdx.y * N_TILE;         // 0 or 128
    const int b  = blockIdx.z;
    const float* specb = spec + (size_t)b * N_FREQ * T_FRAMES;

    float c[4][4][4];
    #pragma unroll
    for (int mi = 0; mi < 4; mi++)
        #pragma unroll
        for (int ni = 0; ni < 4; ni++)
            #pragma unroll
            for (int e = 0; e < 4; e++) c[mi][ni][e] = 0.0f;

    load_stage(specb, g_Bmat, t0, n0, 0, sb + 0 * STAGE_BYTES, tid); CP_COMMIT();
    load_stage(specb, g_Bmat, t0, n0, 1, sb + 1 * STAGE_BYTES, tid); CP_COMMIT();

    for (int p = 0; p < NUM_PAIRS; p++) {
        CP_WAIT1();                 // pair p resident
        __syncthreads();

        const int st = p & 1;
        const float* As = smemf + (size_t)st * (STAGE_BYTES / 4);

        #pragma unroll
        for (int half = 0; half < 2; half++) {
            const float* Bs = As + (SA / 4) * (1 + half);
            const int coff = 4 - half;      // half0: t=j (col m+4); half1: t=j-1
            #pragma unroll
            for (int ks = 0; ks < 4; ks++) {
                const int k0 = ks * 8 + tg;
                uint32_t a[4][4];
                const float* ar0 = As + k0 * SROW + coff;
                const float* ar4 = ar0 + 4 * SROW;
                #pragma unroll
                for (int mi = 0; mi < 4; mi++) {
                    int m = wm * 64 + mi * 16 + g;
                    a[mi][0] = __float_as_uint(ar0[m]);
                    a[mi][1] = __float_as_uint(ar0[m + 8]);
                    a[mi][2] = __float_as_uint(ar4[m]);
                    a[mi][3] = __float_as_uint(ar4[m + 8]);
                }
                uint32_t bf[4][2];
                const float* br0 = Bs + k0 * SROW;
                const float* br4 = br0 + 4 * SROW;
                #pragma unroll
                for (int ni = 0; ni < 4; ni++) {
                    int n = wn * 32 + ni * 8 + g;
                    bf[ni][0] = __float_as_uint(br0[n]);
                    bf[ni][1] = __float_as_uint(br4[n]);
                }
                #pragma unroll
                for (int mi = 0; mi < 4; mi++)
                    #pragma unroll
                    for (int ni = 0; ni < 4; ni++) {
                        asm volatile(
                            "mma.sync.aligned.m16n8k8.row.col.f32.tf32.tf32.f32 "
                            "{%0,%1,%2,%3}, {%4,%5,%6,%7}, {%8,%9}, {%0,%1,%2,%3};"
                            : "+f"(c[mi][ni][0]), "+f"(c[mi][ni][1]),
                              "+f"(c[mi][ni][2]), "+f"(c[mi][ni][3])
                            : "r"(a[mi][0]), "r"(a[mi][1]), "r"(a[mi][2]), "r"(a[mi][3]),
                              "r"(bf[ni][0]), "r"(bf[ni][1]));
                    }
            }
        }
        __syncthreads();

        if (p + 2 < NUM_PAIRS) {
            load_stage(specb, g_Bmat, t0, n0, p + 2, sb + st * STAGE_BYTES, tid);
            CP_COMMIT();
        }
    }

    // epilogue: C fragment -> out[b][j][k2]
    float* outb = out + (size_t)b * OUT_PER_B;
    #pragma unroll
    for (int mi = 0; mi < 4; mi++) {
        int j0 = t0 + wm * 64 + mi * 16 + g;
        #pragma unroll
        for (int ni = 0; ni < 4; ni++) {
            int col = n0 + wn * 32 + ni * 8 + tg * 2;
            if (j0 <= 4096) {
                float2 v = make_float2(c[mi][ni][0], c[mi][ni][1]);
                *(float2*)(outb + (size_t)j0 * 256 + col) = v;
            }
            if (j0 + 8 <= 4096) {
                float2 v = make_float2(c[mi][ni][2], c[mi][ni][3]);
                *(float2*)(outb + (size_t)(j0 + 8) * 256 + col) = v;
            }
        }
    }
}

// ---------------- host launch ----------------
extern "C" void kernel_launch(void* const* d_in, const int* in_sizes, int n_in,
                              void* d_out, int out_size)
{
    const float* spec = (const float*)d_in[0];   // [16,1,256,4096]
    const float* kern = (const float*)d_in[1];   // [512,256]
    float* out = (float*)d_out;

    build_bmat_kernel<<<512, 256>>>(kern);

    cudaFuncSetAttribute(imdct_gemm_kernel,
                         cudaFuncAttributeMaxDynamicSharedMemorySize, SMEM_BYTES);
    imdct_gemm_kernel<<<dim3(33, 2, 16), 256, SMEM_BYTES>>>(spec, out);
}

// round 5
// speedup vs baseline: 1.2402x; 1.2402x over previous
#include <cuda_runtime.h>
#include <cuda_fp16.h>
#include <cstdint>

// ============================================================
// IMDCT as one GEMM (overlap-add folded into K), fp16 datapath:
//   out[b, j, k2] = sum_{kappa<512} A[j,kappa] * Btilde[kappa,k2]
//   A[j, kappa<256]  = spec[b, kappa, j]        (j <= 4095, else 0)
//   A[j, kappa>=256] = spec[b, kappa-256, j-1]  (j >= 1, else 0)
//   Btilde[kappa,k2] = kern[(k2+(kappa<256?0:256))*256+(kappa&255)] * 4/512
//
// fp16 mantissa == tf32 mantissa (10 bits) -> same accuracy, 2x MMA rate,
// half the smem bytes, and ldmatrix.b16 fragment loads. B pre-scaled by
// 2^10 (exact) to avoid fp16 subnormals; epilogue scales by 2^-10.
// A stored m-major (row = t) so the j / j-1 overlap shift is a free
// ldmatrix row-pointer offset.
// ============================================================

#define N_FREQ    256
#define T_FRAMES  4096
#define M_ROWS    4097
#define OUT_PER_B (M_ROWS * 256)

#define M_TILE    128
#define N_TILE    128
#define NUM_PAIRS 8

#define SROWA_B   112                        // A smem row stride bytes (16-al., conflict-free)
#define A_PANEL   (129 * SROWA_B)            // 14448 (rows t0-1 .. t0+127)
#define SROWB_B   272                        // B smem row stride bytes
#define B_PANEL   (32 * SROWB_B)             // 8704
#define STAGE_BYTES 31872                    // A_PANEL + 2*B_PANEL, 16B rounded
#define SMEM_BYTES  (2 * STAGE_BYTES)        // 63744

__device__ __half g_specHT[16 * T_FRAMES * N_FREQ]; // [b][t][f] fp16
__device__ __half g_BmatH[512 * 256];               // [kappa][k2] fp16, x1024

__device__ __forceinline__ uint32_t smem_u32(const void* p) {
    uint32_t a;
    asm("{ .reg .u64 t; cvta.to.shared.u64 t, %1; cvt.u32.u64 %0, t; }" : "=r"(a) : "l"(p));
    return a;
}

// ---------------- prep kernels ----------------
__global__ void build_bmatH_kernel(const float* __restrict__ kern) {
    int i = blockIdx.x * 256 + threadIdx.x;   // 131072
    int kappa = i >> 8;
    int k2    = i & 255;
    int trow  = k2 + ((kappa < 256) ? 0 : 256);
    // (4/512) * 1024 = 8
    g_BmatH[kappa * 256 + k2] = __float2half_rn(kern[trow * 256 + (kappa & 255)] * 8.0f);
}

__global__ void transposeH_kernel(const float* __restrict__ spec) {
    __shared__ float tile[32][33];
    int b  = blockIdx.z;
    int f0 = blockIdx.y * 32;
    int t0 = blockIdx.x * 32;
    int x = threadIdx.x, y = threadIdx.y;
    const float* src = spec + ((size_t)b * N_FREQ + f0) * T_FRAMES + t0;
    #pragma unroll
    for (int i = 0; i < 32; i += 8)
        tile[y + i][x] = src[(size_t)(y + i) * T_FRAMES + x];
    __syncthreads();
    __half* dst = g_specHT + ((size_t)b * T_FRAMES + t0) * N_FREQ + f0;
    #pragma unroll
    for (int i = 0; i < 32; i += 8)
        dst[(size_t)(y + i) * N_FREQ + x] = __float2half_rn(tile[x][y + i]);
}

// ---------------- stage loader ----------------
__device__ __forceinline__ void load_stage(
    int b, int t0, int n0, int pair, uint32_t stage_base, int tid)
{
    const int f0 = pair * 32;
    const __half* HT = g_specHT;
    const __half* BM = g_BmatH;

    // A: 129 rows (t = t0-1+r) x 32 halves (64B = 4x16B)
    for (int i = tid; i < 129 * 4; i += 256) {
        int r  = i >> 2;
        int qq = i & 3;
        int t  = t0 - 1 + r;
        int valid = (t >= 0) && (t < T_FRAMES);
        int tc = valid ? t : 0;
        const char* src = (const char*)(HT + ((size_t)b * T_FRAMES + tc) * N_FREQ + f0) + qq * 16;
        uint32_t dst = stage_base + (uint32_t)(r * SROWA_B + qq * 16);
        uint32_t sz = valid ? 16u : 0u;
        asm volatile("cp.async.cg.shared.global [%0], [%1], 16, %2;"
                     :: "r"(dst), "l"(src), "r"(sz));
    }

    // B: 2 halves x 32 kappa-rows x 128 halves (256B = 16x16B)
    for (int i = tid; i < 1024; i += 256) {
        int h = i >> 9;
        int r = (i >> 4) & 31;
        int q = i & 15;
        const char* src = (const char*)(BM + ((size_t)(h * 256 + f0 + r)) * 256 + n0) + q * 16;
        uint32_t dst = stage_base + (uint32_t)(A_PANEL + h * B_PANEL + r * SROWB_B + q * 16);
        asm volatile("cp.async.cg.shared.global [%0], [%1], 16;"
                     :: "r"(dst), "l"(src));
    }
}

#define CP_COMMIT() asm volatile("cp.async.commit_group;" ::: "memory")
#define CP_WAIT1()  asm volatile("cp.async.wait_group 1;" ::: "memory")

#define LDSM_X4(r0,r1,r2,r3,addr) \
    asm volatile("ldmatrix.sync.aligned.m8n8.x4.shared.b16 {%0,%1,%2,%3}, [%4];" \
        : "=r"(r0), "=r"(r1), "=r"(r2), "=r"(r3) : "r"(addr))

#define LDSM_X4_T(r0,r1,r2,r3,addr) \
    asm volatile("ldmatrix.sync.aligned.m8n8.x4.trans.shared.b16 {%0,%1,%2,%3}, [%4];" \
        : "=r"(r0), "=r"(r1), "=r"(r2), "=r"(r3) : "r"(addr))

// ---------------- main GEMM kernel ----------------
__global__ void __launch_bounds__(256, 2)
imdct_gemm_kernel(float* __restrict__ out)
{
    extern __shared__ __align__(16) char smemc[];
    const uint32_t sb = smem_u32(smemc);

    const int tid = threadIdx.x;
    const int wid = tid >> 5;
    const int lid = tid & 31;
    const int wm  = wid & 1;          // 2 warps along M (64 rows)
    const int wn  = wid >> 1;         // 4 warps along N (32 cols)
    const int tg  = lid & 3;
    const int g   = lid >> 2;

    const int t0 = blockIdx.x * M_TILE;
    const int n0 = blockIdx.y * N_TILE;
    const int b  = blockIdx.z;

    // ldmatrix lane-role decomposition
    const int ltile = lid >> 3;       // 0..3
    const int lsub  = lid & 7;        // row within tile
    const int a_row8 = (ltile & 1) ? 8 : 0;
    const int a_col8 = (ltile & 2) ? 8 : 0;   // same for B n-offset

    float c[4][4][4];
    #pragma unroll
    for (int mi = 0; mi < 4; mi++)
        #pragma unroll
        for (int ni = 0; ni < 4; ni++)
            #pragma unroll
            for (int e = 0; e < 4; e++) c[mi][ni][e] = 0.0f;

    load_stage(b, t0, n0, 0, sb + 0 * STAGE_BYTES, tid); CP_COMMIT();
    load_stage(b, t0, n0, 1, sb + 1 * STAGE_BYTES, tid); CP_COMMIT();

    for (int p = 0; p < NUM_PAIRS; p++) {
        CP_WAIT1();
        __syncthreads();

        const int st = p & 1;
        const uint32_t aBase = sb + st * STAGE_BYTES;
        const uint32_t bBase = aBase + A_PANEL;

        #pragma unroll
        for (int half = 0; half < 2; half++) {
            // A row for m: t = t0 + m - half -> smem row m + 1 - half
            const uint32_t aHalf = aBase + (uint32_t)((1 - half) * SROWA_B);
            const uint32_t bH    = bBase + (uint32_t)(half * B_PANEL);

            #pragma unroll
            for (int ks = 0; ks < 2; ks++) {
                // A fragments: 4 x ldmatrix.x4 (16m x 16k each)
                uint32_t a[4][4];
                #pragma unroll
                for (int mi = 0; mi < 4; mi++) {
                    int row = wm * 64 + mi * 16 + a_row8 + lsub;
                    uint32_t addr = aHalf + (uint32_t)(row * SROWA_B
                                  + (ks * 16 + a_col8) * 2);
                    LDSM_X4(a[mi][0], a[mi][1], a[mi][2], a[mi][3], addr);
                }
                // B fragments: 2 x ldmatrix.x4.trans (16k x 16n each)
                uint32_t bf[4][2];
                #pragma unroll
                for (int pp = 0; pp < 2; pp++) {
                    int krow = ks * 16 + a_row8 + lsub;
                    uint32_t addr = bH + (uint32_t)(krow * SROWB_B
                                  + (wn * 32 + pp * 16 + a_col8) * 2);
                    LDSM_X4_T(bf[2 * pp][0], bf[2 * pp][1],
                              bf[2 * pp + 1][0], bf[2 * pp + 1][1], addr);
                }
                #pragma unroll
                for (int mi = 0; mi < 4; mi++)
                    #pragma unroll
                    for (int ni = 0; ni < 4; ni++) {
                        asm volatile(
                            "mma.sync.aligned.m16n8k16.row.col.f32.f16.f16.f32 "
                            "{%0,%1,%2,%3}, {%4,%5,%6,%7}, {%8,%9}, {%0,%1,%2,%3};"
                            : "+f"(c[mi][ni][0]), "+f"(c[mi][ni][1]),
                              "+f"(c[mi][ni][2]), "+f"(c[mi][ni][3])
                            : "r"(a[mi][0]), "r"(a[mi][1]),
                              "r"(a[mi][2]), "r"(a[mi][3]),
                              "r"(bf[ni][0]), "r"(bf[ni][1]));
                    }
            }
        }
        __syncthreads();

        if (p + 2 < NUM_PAIRS) {
            load_stage(b, t0, n0, p + 2, sb + st * STAGE_BYTES, tid);
            CP_COMMIT();
        }
    }

    // epilogue: scale by 2^-10 and store
    const float scale = 1.0f / 1024.0f;
    float* outb = out + (size_t)b * OUT_PER_B;
    #pragma unroll
    for (int mi = 0; mi < 4; mi++) {
        int j0 = t0 + wm * 64 + mi * 16 + g;
        #pragma unroll
        for (int ni = 0; ni < 4; ni++) {
            int col = n0 + wn * 32 + ni * 8 + tg * 2;
            if (j0 <= 4096) {
                float2 v = make_float2(c[mi][ni][0] * scale, c[mi][ni][1] * scale);
                *(float2*)(outb + (size_t)j0 * 256 + col) = v;
            }
            if (j0 + 8 <= 4096) {
                float2 v = make_float2(c[mi][ni][2] * scale, c[mi][ni][3] * scale);
                *(float2*)(outb + (size_t)(j0 + 8) * 256 + col) = v;
            }
        }
    }
}

// ---------------- host launch ----------------
extern "C" void kernel_launch(void* const* d_in, const int* in_sizes, int n_in,
                              void* d_out, int out_size)
{
    const float* spec = (const float*)d_in[0];   // [16,1,256,4096]
    const float* kern = (const float*)d_in[1];   // [512,256]
    float* out = (float*)d_out;

    build_bmatH_kernel<<<512, 256>>>(kern);
    transposeH_kernel<<<dim3(T_FRAMES / 32, N_FREQ / 32, 16), dim3(32, 8)>>>(spec);

    cudaFuncSetAttribute(imdct_gemm_kernel,
                         cudaFuncAttributeMaxDynamicSharedMemorySize, SMEM_BYTES);
    imdct_gemm_kernel<<<dim3(33, 2, 16), 256, SMEM_BYTES>>>(out);
}